// round 16
// baseline (speedup 1.0000x reference)
#include <cuda_runtime.h>
#include <cuda_fp16.h>
#include <mma.h>
#include <cstdint>

using namespace nvcuda;

#define N_NODES 50000
#define N_EDGES 800000
#define NGRAPHS 8
#define NCLASSES 10
#define M_PAD 50176          // 784 * 64

typedef unsigned long long ull;

__device__ __forceinline__ void red_add_v4(float* p, float a, float b, float c, float d) {
    asm volatile("red.global.add.v4.f32 [%0], {%1, %2, %3, %4};"
                 :: "l"(p), "f"(a), "f"(b), "f"(c), "f"(d) : "memory");
}
__device__ __forceinline__ ull f32x2_fma(ull a, ull b, ull c) {
    ull d;
    asm("fma.rn.f32x2 %0, %1, %2, %3;" : "=l"(d) : "l"(a), "l"(b), "l"(c));
    return d;
}
__device__ __forceinline__ ull pack2(float x) {
    ull r;
    asm("mov.b64 %0, {%1, %1};" : "=l"(r) : "f"(x));
    return r;
}
__device__ __forceinline__ float2 unpack2(ull v) {
    float2 f;
    asm("mov.b64 {%0, %1}, %2;" : "=f"(f.x), "=f"(f.y) : "l"(v));
    return f;
}
__device__ __forceinline__ ull h2_to_ull(unsigned int h2) {
    float2 f = __half22float2(*(__half2*)&h2);
    return *(ull*)&f;
}

// ---------------- scratch ----------------------------------------------------------
__device__ __align__(16) float   g_h0  [N_NODES * 16];
__device__ __align__(16) float4  g_hu1 [N_NODES];
__device__ __align__(16) __half2 g_xw1h[N_NODES * 64];         // pair-major
__device__ __align__(16) float   g_agg1[N_NODES * 32];
__device__ __align__(16) float   g_cnt [N_NODES];
__device__ __align__(16) float4  g_hu2 [N_NODES];
__device__ __align__(16) __half  g_h1h [M_PAD * 32];           // fp16 A operand
__device__ __align__(16) __half  g_w2h [32 * 256];             // fp16 w2 (pre-converted)
__device__ __align__(16) __half  g_xw2r[(size_t)M_PAD * 256];  // row-major fp16
__device__ __align__(16) float   g_agg2[N_NODES * 64];
__device__ __align__(16) float   g_pool[NGRAPHS * 64];
__device__ __align__(16) float   g_gcnt[NGRAPHS];

// ---------------- kernel A: h0 = relu(x@fc0+b); xw1 = h0@w1; hu1 = h0@u1 ----------
__global__ void k_fc0_xw1(const float* __restrict__ x,
                          const float* __restrict__ fc0_w,
                          const float* __restrict__ fc0_b,
                          const float* __restrict__ w1,
                          const float* __restrict__ u1) {
    __shared__ float2 w1s[16 * 64];
    __shared__ float  u1s[64];
    const float2* w1g = (const float2*)w1;
    for (int i = threadIdx.x; i < 16 * 64; i += blockDim.x) w1s[i] = w1g[i];
    if (threadIdx.x < 64) u1s[threadIdx.x] = u1[threadIdx.x];
    __syncthreads();

    int w = threadIdx.x >> 5, lane = threadIdx.x & 31;
    int n0 = (blockIdx.x * 8 + w) * 4;
    if (n0 >= N_NODES) return;

    float hn[4];
    #pragma unroll
    for (int m = 0; m < 4; m++) {
        int n = n0 + m;
        float v = 0.f;
        if (n < N_NODES && lane < 16) {
            v = fc0_b[lane];
            #pragma unroll
            for (int j = 0; j < 3; j++) v += x[n * 3 + j] * fc0_w[j * 16 + lane];
            v = fmaxf(v, 0.f);
            g_h0[n * 16 + lane] = v;
        }
        hn[m] = v;
    }
    __syncwarp();

    #pragma unroll
    for (int m = 0; m < 4; m++) {
        int n = n0 + m;
        if (n >= N_NODES) break;
        int k = lane & 15;
        float a0 = hn[m] * u1s[k * 4 + 0];
        float a1 = hn[m] * u1s[k * 4 + 1];
        float a2 = hn[m] * u1s[k * 4 + 2];
        float a3 = hn[m] * u1s[k * 4 + 3];
        #pragma unroll
        for (int off = 16; off; off >>= 1) {
            a0 += __shfl_xor_sync(0xffffffffu, a0, off);
            a1 += __shfl_xor_sync(0xffffffffu, a1, off);
            a2 += __shfl_xor_sync(0xffffffffu, a2, off);
            a3 += __shfl_xor_sync(0xffffffffu, a3, off);
        }
        if (lane == 0) g_hu1[n] = make_float4(a0, a1, a2, a3);
    }

    const ull* w1u = (const ull*)w1s;
    ull acc[4][2];
    #pragma unroll
    for (int m = 0; m < 4; m++) { acc[m][0] = 0ull; acc[m][1] = 0ull; }

    #pragma unroll
    for (int k = 0; k < 16; k++) {
        ull wk0 = w1u[k * 64 + lane];
        ull wk1 = w1u[k * 64 + 32 + lane];
        #pragma unroll
        for (int m = 0; m < 4; m++) {
            ull hk = pack2(__shfl_sync(0xffffffffu, hn[m], k));
            acc[m][0] = f32x2_fma(hk, wk0, acc[m][0]);
            acc[m][1] = f32x2_fma(hk, wk1, acc[m][1]);
        }
    }
    int p = lane & 15, hh = lane >> 4;
    #pragma unroll
    for (int m = 0; m < 4; m++) {
        int n = n0 + m;
        if (n < N_NODES) {
            g_xw1h[(size_t)n * 64 + p * 4 + hh]     = __float22half2_rn(unpack2(acc[m][0]));
            g_xw1h[(size_t)n * 64 + p * 4 + 2 + hh] = __float22half2_rn(unpack2(acc[m][1]));
        }
    }
}

// ---------------- kernel B: conv1 edge pass (8 edges/warp; 2 batched) --------------
__global__ void k_conv1_edge(const int* __restrict__ ei,
                             const float* __restrict__ c1) {
    float cc0 = __ldg(&c1[0]), cc1 = __ldg(&c1[1]), cc2 = __ldg(&c1[2]), cc3 = __ldg(&c1[3]);
    int w = threadIdx.x >> 5, lane = threadIdx.x & 31;
    int sub = lane >> 3, j = lane & 7;
    int e0 = (blockIdx.x * 8 + w) * 8 + sub * 2;
    if (e0 >= N_EDGES) return;
    int e1 = e0 + 1;

    int s0 = ei[e0], t0 = ei[N_EDGES + e0];
    int s1 = ei[e1], t1 = ei[N_EDGES + e1];

    float4 A0 = g_hu1[s0], B0 = g_hu1[t0];
    float4 A1 = g_hu1[s1], B1 = g_hu1[t1];

    const uint4* x0 = (const uint4*)(g_xw1h + (size_t)s0 * 64);
    const uint4* x1 = (const uint4*)(g_xw1h + (size_t)s1 * 64);
    uint4 P0 = x0[2 * j], Q0 = x0[2 * j + 1];
    uint4 P1 = x1[2 * j], Q1 = x1[2 * j + 1];

    float l0 = A0.x - B0.x + cc0, l1 = A0.y - B0.y + cc1;
    float l2 = A0.z - B0.z + cc2, l3 = A0.w - B0.w + cc3;
    float m = fmaxf(fmaxf(l0, l1), fmaxf(l2, l3));
    float q0 = __expf(l0 - m), q1 = __expf(l1 - m), q2 = __expf(l2 - m), q3 = __expf(l3 - m);
    float inv = 1.f / (q0 + q1 + q2 + q3);
    ull qa0 = pack2(q0 * inv), qa1 = pack2(q1 * inv), qa2 = pack2(q2 * inv), qa3 = pack2(q3 * inv);

    float k0 = A1.x - B1.x + cc0, k1 = A1.y - B1.y + cc1;
    float k2 = A1.z - B1.z + cc2, k3 = A1.w - B1.w + cc3;
    float mm = fmaxf(fmaxf(k0, k1), fmaxf(k2, k3));
    float r0 = __expf(k0 - mm), r1 = __expf(k1 - mm), r2 = __expf(k2 - mm), r3 = __expf(k3 - mm);
    float rinv = 1.f / (r0 + r1 + r2 + r3);
    ull qb0 = pack2(r0 * rinv), qb1 = pack2(r1 * rinv), qb2 = pack2(r2 * rinv), qb3 = pack2(r3 * rinv);

    ull m0a = 0ull, m0b = 0ull, m1a = 0ull, m1b = 0ull;
    m0a = f32x2_fma(qa0, h2_to_ull(P0.x), m0a);
    m0a = f32x2_fma(qa1, h2_to_ull(P0.y), m0a);
    m0a = f32x2_fma(qa2, h2_to_ull(P0.z), m0a);
    m0a = f32x2_fma(qa3, h2_to_ull(P0.w), m0a);
    m0b = f32x2_fma(qa0, h2_to_ull(Q0.x), m0b);
    m0b = f32x2_fma(qa1, h2_to_ull(Q0.y), m0b);
    m0b = f32x2_fma(qa2, h2_to_ull(Q0.z), m0b);
    m0b = f32x2_fma(qa3, h2_to_ull(Q0.w), m0b);
    m1a = f32x2_fma(qb0, h2_to_ull(P1.x), m1a);
    m1a = f32x2_fma(qb1, h2_to_ull(P1.y), m1a);
    m1a = f32x2_fma(qb2, h2_to_ull(P1.z), m1a);
    m1a = f32x2_fma(qb3, h2_to_ull(P1.w), m1a);
    m1b = f32x2_fma(qb0, h2_to_ull(Q1.x), m1b);
    m1b = f32x2_fma(qb1, h2_to_ull(Q1.y), m1b);
    m1b = f32x2_fma(qb2, h2_to_ull(Q1.z), m1b);
    m1b = f32x2_fma(qb3, h2_to_ull(Q1.w), m1b);

    float2 u0 = unpack2(m0a), v0 = unpack2(m0b);
    float2 u1v = unpack2(m1a), v1 = unpack2(m1b);
    red_add_v4(&g_agg1[(size_t)t0 * 32 + 4 * j], u0.x, u0.y, v0.x, v0.y);
    red_add_v4(&g_agg1[(size_t)t1 * 32 + 4 * j], u1v.x, u1v.y, v1.x, v1.y);
    if (j == 0) {
        atomicAdd(&g_cnt[t0], 1.0f);
        atomicAdd(&g_cnt[t1], 1.0f);
    }
}

// ---------------- kernel H: h1 (fp16) + hu2 + w2 pre-conversion --------------------
__global__ void k_h1(const float* __restrict__ b1,
                     const float* __restrict__ u2,
                     const float* __restrict__ w2) {
    __shared__ float u2s[128];
    if (threadIdx.x < 128) u2s[threadIdx.x] = u2[threadIdx.x];
    __syncthreads();

    // block 0 also converts w2 -> fp16 (overlapped with node work of other blocks)
    if (blockIdx.x == 0) {
        for (int i = threadIdx.x; i < 32 * 256; i += blockDim.x)
            g_w2h[i] = __float2half(w2[i]);
    }

    int w = threadIdx.x >> 5, lane = threadIdx.x & 31;
    int n = blockIdx.x * 8 + w;
    if (n >= N_NODES) return;

    float cnt = fmaxf(g_cnt[n], 1.f);
    float h = fmaxf(g_agg1[(size_t)n * 32 + lane] / cnt + b1[lane], 0.f);
    g_h1h[(size_t)n * 32 + lane] = __float2half(h);

    float a0 = h * u2s[lane * 4 + 0];
    float a1 = h * u2s[lane * 4 + 1];
    float a2 = h * u2s[lane * 4 + 2];
    float a3 = h * u2s[lane * 4 + 3];
    #pragma unroll
    for (int off = 16; off; off >>= 1) {
        a0 += __shfl_xor_sync(0xffffffffu, a0, off);
        a1 += __shfl_xor_sync(0xffffffffu, a1, off);
        a2 += __shfl_xor_sync(0xffffffffu, a2, off);
        a3 += __shfl_xor_sync(0xffffffffu, a3, off);
    }
    if (lane == 0) g_hu2[n] = make_float4(a0, a1, a2, a3);
}

// ---------------- kernel M: xw2 = h1 @ w2 via wmma (HMMA), 64 rows/block -----------
// No shared staging: B fragments loaded once per warp straight from global g_w2h.
// 8 warps; warp w: col group (w & 3)*64, row tiles (w>>2), (w>>2)+2 (2 tiles).
__global__ void k_xw2_wmma() {
    int w = threadIdx.x >> 5;
    int col0 = (w & 3) * 64;
    int rsub = w >> 2;                 // 0 or 1

    wmma::fragment<wmma::matrix_b, 16, 16, 16, __half, wmma::row_major> b[4][2];
    #pragma unroll
    for (int c = 0; c < 4; c++) {
        wmma::load_matrix_sync(b[c][0], g_w2h + col0 + c * 16, 256);
        wmma::load_matrix_sync(b[c][1], g_w2h + 16 * 256 + col0 + c * 16, 256);
    }

    size_t base = (size_t)blockIdx.x * 64;
    #pragma unroll
    for (int rt = rsub; rt < 4; rt += 2) {
        size_t row0 = base + (size_t)rt * 16;
        wmma::fragment<wmma::matrix_a, 16, 16, 16, __half, wmma::row_major> a0, a1;
        wmma::load_matrix_sync(a0, g_h1h + row0 * 32, 32);
        wmma::load_matrix_sync(a1, g_h1h + row0 * 32 + 16, 32);
        #pragma unroll
        for (int c = 0; c < 4; c++) {
            wmma::fragment<wmma::accumulator, 16, 16, 16, __half> acc;
            wmma::fill_fragment(acc, __float2half(0.f));
            wmma::mma_sync(acc, a0, b[c][0], acc);
            wmma::mma_sync(acc, a1, b[c][1], acc);
            wmma::store_matrix_sync(g_xw2r + row0 * 256 + col0 + c * 16, acc, 256,
                                    wmma::mem_row_major);
        }
    }
}

// ---------------- kernel D: conv2 edge pass (row-major fp16 gather) ----------------
__global__ void k_conv2_edge(const int* __restrict__ ei,
                             const float* __restrict__ c2) {
    float cc0 = __ldg(&c2[0]), cc1 = __ldg(&c2[1]), cc2 = __ldg(&c2[2]), cc3 = __ldg(&c2[3]);
    int w = threadIdx.x >> 5, lane = threadIdx.x & 31;
    int sub = lane >> 4, j = lane & 15;
    int e0 = (blockIdx.x * 8 + w) * 4 + sub * 2;
    if (e0 >= N_EDGES) return;
    int e1 = e0 + 1;

    int s0 = ei[e0], t0 = ei[N_EDGES + e0];
    int s1 = ei[e1], t1 = ei[N_EDGES + e1];

    float4 A0 = g_hu2[s0], B0 = g_hu2[t0];
    float4 A1 = g_hu2[s1], B1 = g_hu2[t1];

    const uint2* x0 = (const uint2*)(g_xw2r + (size_t)s0 * 256);
    const uint2* x1 = (const uint2*)(g_xw2r + (size_t)s1 * 256);
    uint2 w00 = x0[j], w01 = x0[16 + j], w02 = x0[32 + j], w03 = x0[48 + j];
    uint2 w10 = x1[j], w11 = x1[16 + j], w12 = x1[32 + j], w13 = x1[48 + j];

    float l0 = A0.x - B0.x + cc0, l1 = A0.y - B0.y + cc1;
    float l2 = A0.z - B0.z + cc2, l3 = A0.w - B0.w + cc3;
    float m = fmaxf(fmaxf(l0, l1), fmaxf(l2, l3));
    float q0 = __expf(l0 - m), q1 = __expf(l1 - m), q2 = __expf(l2 - m), q3 = __expf(l3 - m);
    float inv = 1.f / (q0 + q1 + q2 + q3);
    ull qa0 = pack2(q0 * inv), qa1 = pack2(q1 * inv), qa2 = pack2(q2 * inv), qa3 = pack2(q3 * inv);

    float k0 = A1.x - B1.x + cc0, k1 = A1.y - B1.y + cc1;
    float k2 = A1.z - B1.z + cc2, k3 = A1.w - B1.w + cc3;
    float mm = fmaxf(fmaxf(k0, k1), fmaxf(k2, k3));
    float r0 = __expf(k0 - mm), r1 = __expf(k1 - mm), r2 = __expf(k2 - mm), r3 = __expf(k3 - mm);
    float rinv = 1.f / (r0 + r1 + r2 + r3);
    ull qb0 = pack2(r0 * rinv), qb1 = pack2(r1 * rinv), qb2 = pack2(r2 * rinv), qb3 = pack2(r3 * rinv);

    ull m0a = 0ull, m0b = 0ull, m1a = 0ull, m1b = 0ull;
    m0a = f32x2_fma(qa0, h2_to_ull(w00.x), m0a);
    m0b = f32x2_fma(qa0, h2_to_ull(w00.y), m0b);
    m0a = f32x2_fma(qa1, h2_to_ull(w01.x), m0a);
    m0b = f32x2_fma(qa1, h2_to_ull(w01.y), m0b);
    m0a = f32x2_fma(qa2, h2_to_ull(w02.x), m0a);
    m0b = f32x2_fma(qa2, h2_to_ull(w02.y), m0b);
    m0a = f32x2_fma(qa3, h2_to_ull(w03.x), m0a);
    m0b = f32x2_fma(qa3, h2_to_ull(w03.y), m0b);
    m1a = f32x2_fma(qb0, h2_to_ull(w10.x), m1a);
    m1b = f32x2_fma(qb0, h2_to_ull(w10.y), m1b);
    m1a = f32x2_fma(qb1, h2_to_ull(w11.x), m1a);
    m1b = f32x2_fma(qb1, h2_to_ull(w11.y), m1b);
    m1a = f32x2_fma(qb2, h2_to_ull(w12.x), m1a);
    m1b = f32x2_fma(qb2, h2_to_ull(w12.y), m1b);
    m1a = f32x2_fma(qb3, h2_to_ull(w13.x), m1a);
    m1b = f32x2_fma(qb3, h2_to_ull(w13.y), m1b);

    float2 u0 = unpack2(m0a), v0 = unpack2(m0b);
    float2 u1v = unpack2(m1a), v1 = unpack2(m1b);
    red_add_v4(&g_agg2[(size_t)t0 * 64 + 4 * j], u0.x, u0.y, v0.x, v0.y);
    red_add_v4(&g_agg2[(size_t)t1 * 64 + 4 * j], u1v.x, u1v.y, v1.x, v1.y);
}

// ---------------- kernel E: h2 epilogue + staged global pooling --------------------
__global__ void k_conv2_epi_pool(const float* __restrict__ b2,
                                 const int* __restrict__ batch) {
    __shared__ float pools[NGRAPHS * 64];
    __shared__ float gcnts[NGRAPHS];
    for (int i = threadIdx.x; i < NGRAPHS * 64; i += blockDim.x) pools[i] = 0.f;
    if (threadIdx.x < NGRAPHS) gcnts[threadIdx.x] = 0.f;
    __syncthreads();

    int w = threadIdx.x >> 5, lane = threadIdx.x & 31;
    int n = blockIdx.x * 8 + w;
    if (n < N_NODES) {
        float cnt = fmaxf(g_cnt[n], 1.f);
        int g = batch[n];
        float h0v = fmaxf(g_agg2[(size_t)n * 64 + lane]      / cnt + b2[lane],      0.f);
        float h1v = fmaxf(g_agg2[(size_t)n * 64 + 32 + lane] / cnt + b2[32 + lane], 0.f);
        atomicAdd(&pools[g * 64 + lane],      h0v);
        atomicAdd(&pools[g * 64 + 32 + lane], h1v);
        if (lane == 0) atomicAdd(&gcnts[g], 1.f);
    }
    __syncthreads();
    for (int i = threadIdx.x; i < NGRAPHS * 64; i += blockDim.x) atomicAdd(&g_pool[i], pools[i]);
    if (threadIdx.x < NGRAPHS) atomicAdd(&g_gcnt[threadIdx.x], gcnts[threadIdx.x]);
}

// ---------------- kernel F: head ---------------------------------------------------
__global__ void k_head(const float* __restrict__ fc1_w,
                       const float* __restrict__ fc1_b,
                       float* __restrict__ out) {
    int tid = threadIdx.x;
    if (tid < NGRAPHS * NCLASSES) {
        int g = tid / NCLASSES, j = tid % NCLASSES;
        float invn = 1.f / fmaxf(g_gcnt[g], 1.f);
        float acc = 0.f;
        #pragma unroll
        for (int c = 0; c < 64; c++) acc += g_pool[g * 64 + c] * fc1_w[c * NCLASSES + j];
        out[tid] = acc * invn + fc1_b[j];
    }
}

// ---------------- launch ------------------------------------------------------------
extern "C" void kernel_launch(void* const* d_in, const int* in_sizes, int n_in,
                              void* d_out, int out_size) {
    const float* x     = (const float*)d_in[0];
    const int*   ei    = (const int*)d_in[1];
    const int*   batch = (const int*)d_in[2];
    const float* fc0_w = (const float*)d_in[3];
    const float* fc0_b = (const float*)d_in[4];
    const float* u1    = (const float*)d_in[5];
    const float* c1    = (const float*)d_in[6];
    const float* w1    = (const float*)d_in[7];
    const float* b1    = (const float*)d_in[8];
    const float* u2    = (const float*)d_in[9];
    const float* c2    = (const float*)d_in[10];
    const float* w2    = (const float*)d_in[11];
    const float* b2    = (const float*)d_in[12];
    const float* fc1_w = (const float*)d_in[13];
    const float* fc1_b = (const float*)d_in[14];
    float* out = (float*)d_out;

    void *p_agg1, *p_agg2, *p_cnt, *p_pool, *p_gcnt, *p_h1h;
    cudaGetSymbolAddress(&p_agg1, g_agg1);
    cudaGetSymbolAddress(&p_agg2, g_agg2);
    cudaGetSymbolAddress(&p_cnt,  g_cnt);
    cudaGetSymbolAddress(&p_pool, g_pool);
    cudaGetSymbolAddress(&p_gcnt, g_gcnt);
    cudaGetSymbolAddress(&p_h1h,  g_h1h);
    cudaMemsetAsync(p_agg1, 0, sizeof(float) * N_NODES * 32, 0);
    cudaMemsetAsync(p_agg2, 0, sizeof(float) * N_NODES * 64, 0);
    cudaMemsetAsync(p_cnt,  0, sizeof(float) * N_NODES, 0);
    cudaMemsetAsync(p_pool, 0, sizeof(float) * NGRAPHS * 64, 0);
    cudaMemsetAsync(p_gcnt, 0, sizeof(float) * NGRAPHS, 0);
    cudaMemsetAsync((char*)p_h1h + (size_t)N_NODES * 32 * sizeof(__half), 0,
                    (size_t)(M_PAD - N_NODES) * 32 * sizeof(__half), 0);

    k_fc0_xw1<<<(N_NODES + 31) / 32, 256>>>(x, fc0_w, fc0_b, w1, u1);
    k_conv1_edge<<<(N_EDGES + 63) / 64, 256>>>(ei, c1);
    k_h1<<<(N_NODES + 7) / 8, 256>>>(b1, u2, w2);
    k_xw2_wmma<<<M_PAD / 64, 256>>>();
    k_conv2_edge<<<(N_EDGES + 31) / 32, 256>>>(ei, c2);
    k_conv2_epi_pool<<<(N_NODES + 7) / 8, 256>>>(b2, batch);
    k_head<<<1, 128>>>(fc1_w, fc1_b, out);
}

// round 17
// speedup vs baseline: 1.0277x; 1.0277x over previous
#include <cuda_runtime.h>
#include <cuda_fp16.h>
#include <mma.h>
#include <cstdint>

using namespace nvcuda;

#define N_NODES 50000
#define N_EDGES 800000
#define NGRAPHS 8
#define NCLASSES 10
#define M_PAD 50176          // 784 * 64

typedef unsigned long long ull;

__device__ __forceinline__ void red_add_v4(float* p, float a, float b, float c, float d) {
    asm volatile("red.global.add.v4.f32 [%0], {%1, %2, %3, %4};"
                 :: "l"(p), "f"(a), "f"(b), "f"(c), "f"(d) : "memory");
}
__device__ __forceinline__ ull f32x2_fma(ull a, ull b, ull c) {
    ull d;
    asm("fma.rn.f32x2 %0, %1, %2, %3;" : "=l"(d) : "l"(a), "l"(b), "l"(c));
    return d;
}
__device__ __forceinline__ ull pack2(float x) {
    ull r;
    asm("mov.b64 %0, {%1, %1};" : "=l"(r) : "f"(x));
    return r;
}
__device__ __forceinline__ float2 unpack2(ull v) {
    float2 f;
    asm("mov.b64 {%0, %1}, %2;" : "=f"(f.x), "=f"(f.y) : "l"(v));
    return f;
}
__device__ __forceinline__ ull h2_to_ull(unsigned int h2) {
    float2 f = __half22float2(*(__half2*)&h2);
    return *(ull*)&f;
}

// ---------------- scratch ----------------------------------------------------------
__device__ __align__(16) float   g_h0  [N_NODES * 16];
__device__ __align__(16) float4  g_hu1 [N_NODES];
__device__ __align__(16) __half2 g_xw1h[N_NODES * 64];         // pair-major
__device__ __align__(16) float   g_agg1[N_NODES * 32];
__device__ __align__(16) float   g_cnt [N_NODES];
__device__ __align__(16) float4  g_hu2 [N_NODES];
__device__ __align__(16) __half  g_h1h [M_PAD * 32];           // fp16 A operand
__device__ __align__(16) __half  g_w2h [32 * 256];             // fp16 w2
__device__ __align__(16) __half  g_xw2r[(size_t)M_PAD * 256];  // row-major fp16
__device__ __align__(16) float   g_agg2[N_NODES * 64];
__device__ __align__(16) float   g_pool[NGRAPHS * 64];
__device__ __align__(16) float   g_gcnt[NGRAPHS];
__device__ int g_done;

// ---------------- kernel A: zero agg1/cnt; h0; xw1 = h0@w1; hu1 = h0@u1 -----------
__global__ void k_fc0_xw1(const float* __restrict__ x,
                          const float* __restrict__ fc0_w,
                          const float* __restrict__ fc0_b,
                          const float* __restrict__ w1,
                          const float* __restrict__ u1) {
    // fused zeroing of agg1 (400k float4) + cnt (12.5k float4)
    {
        int idx = blockIdx.x * blockDim.x + threadIdx.x;
        int stride = gridDim.x * blockDim.x;
        float4 z = make_float4(0.f, 0.f, 0.f, 0.f);
        for (int i = idx; i < N_NODES * 8; i += stride) ((float4*)g_agg1)[i] = z;
        for (int i = idx; i < N_NODES / 4 + 1; i += stride)
            if (i * 4 < N_NODES) ((float4*)g_cnt)[i] = z;
    }

    __shared__ float2 w1s[16 * 64];
    __shared__ float  u1s[64];
    const float2* w1g = (const float2*)w1;
    for (int i = threadIdx.x; i < 16 * 64; i += blockDim.x) w1s[i] = w1g[i];
    if (threadIdx.x < 64) u1s[threadIdx.x] = u1[threadIdx.x];
    __syncthreads();

    int w = threadIdx.x >> 5, lane = threadIdx.x & 31;
    int n0 = (blockIdx.x * 8 + w) * 4;
    if (n0 >= N_NODES) return;

    float hn[4];
    #pragma unroll
    for (int m = 0; m < 4; m++) {
        int n = n0 + m;
        float v = 0.f;
        if (n < N_NODES && lane < 16) {
            v = fc0_b[lane];
            #pragma unroll
            for (int j = 0; j < 3; j++) v += x[n * 3 + j] * fc0_w[j * 16 + lane];
            v = fmaxf(v, 0.f);
            g_h0[n * 16 + lane] = v;
        }
        hn[m] = v;
    }
    __syncwarp();

    #pragma unroll
    for (int m = 0; m < 4; m++) {
        int n = n0 + m;
        if (n >= N_NODES) break;
        int k = lane & 15;
        float a0 = hn[m] * u1s[k * 4 + 0];
        float a1 = hn[m] * u1s[k * 4 + 1];
        float a2 = hn[m] * u1s[k * 4 + 2];
        float a3 = hn[m] * u1s[k * 4 + 3];
        #pragma unroll
        for (int off = 16; off; off >>= 1) {
            a0 += __shfl_xor_sync(0xffffffffu, a0, off);
            a1 += __shfl_xor_sync(0xffffffffu, a1, off);
            a2 += __shfl_xor_sync(0xffffffffu, a2, off);
            a3 += __shfl_xor_sync(0xffffffffu, a3, off);
        }
        if (lane == 0) g_hu1[n] = make_float4(a0, a1, a2, a3);
    }

    const ull* w1u = (const ull*)w1s;
    ull acc[4][2];
    #pragma unroll
    for (int m = 0; m < 4; m++) { acc[m][0] = 0ull; acc[m][1] = 0ull; }

    #pragma unroll
    for (int k = 0; k < 16; k++) {
        ull wk0 = w1u[k * 64 + lane];
        ull wk1 = w1u[k * 64 + 32 + lane];
        #pragma unroll
        for (int m = 0; m < 4; m++) {
            ull hk = pack2(__shfl_sync(0xffffffffu, hn[m], k));
            acc[m][0] = f32x2_fma(hk, wk0, acc[m][0]);
            acc[m][1] = f32x2_fma(hk, wk1, acc[m][1]);
        }
    }
    int p = lane & 15, hh = lane >> 4;
    #pragma unroll
    for (int m = 0; m < 4; m++) {
        int n = n0 + m;
        if (n < N_NODES) {
            g_xw1h[(size_t)n * 64 + p * 4 + hh]     = __float22half2_rn(unpack2(acc[m][0]));
            g_xw1h[(size_t)n * 64 + p * 4 + 2 + hh] = __float22half2_rn(unpack2(acc[m][1]));
        }
    }
}

// ---------------- kernel B: conv1 edge pass (8 edges/warp; 2 batched) --------------
__global__ void k_conv1_edge(const int* __restrict__ ei,
                             const float* __restrict__ c1) {
    float cc0 = __ldg(&c1[0]), cc1 = __ldg(&c1[1]), cc2 = __ldg(&c1[2]), cc3 = __ldg(&c1[3]);
    int w = threadIdx.x >> 5, lane = threadIdx.x & 31;
    int sub = lane >> 3, j = lane & 7;
    int e0 = (blockIdx.x * 8 + w) * 8 + sub * 2;
    if (e0 >= N_EDGES) return;
    int e1 = e0 + 1;

    int s0 = ei[e0], t0 = ei[N_EDGES + e0];
    int s1 = ei[e1], t1 = ei[N_EDGES + e1];

    float4 A0 = g_hu1[s0], B0 = g_hu1[t0];
    float4 A1 = g_hu1[s1], B1 = g_hu1[t1];

    const uint4* x0 = (const uint4*)(g_xw1h + (size_t)s0 * 64);
    const uint4* x1 = (const uint4*)(g_xw1h + (size_t)s1 * 64);
    uint4 P0 = x0[2 * j], Q0 = x0[2 * j + 1];
    uint4 P1 = x1[2 * j], Q1 = x1[2 * j + 1];

    float l0 = A0.x - B0.x + cc0, l1 = A0.y - B0.y + cc1;
    float l2 = A0.z - B0.z + cc2, l3 = A0.w - B0.w + cc3;
    float m = fmaxf(fmaxf(l0, l1), fmaxf(l2, l3));
    float q0 = __expf(l0 - m), q1 = __expf(l1 - m), q2 = __expf(l2 - m), q3 = __expf(l3 - m);
    float inv = 1.f / (q0 + q1 + q2 + q3);
    ull qa0 = pack2(q0 * inv), qa1 = pack2(q1 * inv), qa2 = pack2(q2 * inv), qa3 = pack2(q3 * inv);

    float k0 = A1.x - B1.x + cc0, k1 = A1.y - B1.y + cc1;
    float k2 = A1.z - B1.z + cc2, k3 = A1.w - B1.w + cc3;
    float mm = fmaxf(fmaxf(k0, k1), fmaxf(k2, k3));
    float r0 = __expf(k0 - mm), r1 = __expf(k1 - mm), r2 = __expf(k2 - mm), r3 = __expf(k3 - mm);
    float rinv = 1.f / (r0 + r1 + r2 + r3);
    ull qb0 = pack2(r0 * rinv), qb1 = pack2(r1 * rinv), qb2 = pack2(r2 * rinv), qb3 = pack2(r3 * rinv);

    ull m0a = 0ull, m0b = 0ull, m1a = 0ull, m1b = 0ull;
    m0a = f32x2_fma(qa0, h2_to_ull(P0.x), m0a);
    m0a = f32x2_fma(qa1, h2_to_ull(P0.y), m0a);
    m0a = f32x2_fma(qa2, h2_to_ull(P0.z), m0a);
    m0a = f32x2_fma(qa3, h2_to_ull(P0.w), m0a);
    m0b = f32x2_fma(qa0, h2_to_ull(Q0.x), m0b);
    m0b = f32x2_fma(qa1, h2_to_ull(Q0.y), m0b);
    m0b = f32x2_fma(qa2, h2_to_ull(Q0.z), m0b);
    m0b = f32x2_fma(qa3, h2_to_ull(Q0.w), m0b);
    m1a = f32x2_fma(qb0, h2_to_ull(P1.x), m1a);
    m1a = f32x2_fma(qb1, h2_to_ull(P1.y), m1a);
    m1a = f32x2_fma(qb2, h2_to_ull(P1.z), m1a);
    m1a = f32x2_fma(qb3, h2_to_ull(P1.w), m1a);
    m1b = f32x2_fma(qb0, h2_to_ull(Q1.x), m1b);
    m1b = f32x2_fma(qb1, h2_to_ull(Q1.y), m1b);
    m1b = f32x2_fma(qb2, h2_to_ull(Q1.z), m1b);
    m1b = f32x2_fma(qb3, h2_to_ull(Q1.w), m1b);

    float2 u0 = unpack2(m0a), v0 = unpack2(m0b);
    float2 u1v = unpack2(m1a), v1 = unpack2(m1b);
    red_add_v4(&g_agg1[(size_t)t0 * 32 + 4 * j], u0.x, u0.y, v0.x, v0.y);
    red_add_v4(&g_agg1[(size_t)t1 * 32 + 4 * j], u1v.x, u1v.y, v1.x, v1.y);
    if (j == 0) {
        atomicAdd(&g_cnt[t0], 1.0f);
        atomicAdd(&g_cnt[t1], 1.0f);
    }
}

// ---------------- kernel H: h1 (fp16) + hu2 + w2 conversion + small zeros ----------
__global__ void k_h1(const float* __restrict__ b1,
                     const float* __restrict__ u2,
                     const float* __restrict__ w2) {
    __shared__ float u2s[128];
    if (threadIdx.x < 128) u2s[threadIdx.x] = u2[threadIdx.x];
    __syncthreads();

    if (blockIdx.x == 0) {
        // w2 -> fp16
        for (int i = threadIdx.x; i < 32 * 256; i += blockDim.x)
            g_w2h[i] = __float2half(w2[i]);
        // pool/gcnt/done zero
        for (int i = threadIdx.x; i < NGRAPHS * 64; i += blockDim.x) g_pool[i] = 0.f;
        if (threadIdx.x < NGRAPHS) g_gcnt[threadIdx.x] = 0.f;
        if (threadIdx.x == 0) g_done = 0;
    } else if (blockIdx.x == 1) {
        // h1h tail rows zero: (M_PAD - N_NODES) * 32 halves = 5632 = 1408 uint
        unsigned* tail = (unsigned*)(g_h1h + (size_t)N_NODES * 32);
        for (int i = threadIdx.x; i < (M_PAD - N_NODES) * 16; i += blockDim.x) tail[i] = 0u;
    }

    int w = threadIdx.x >> 5, lane = threadIdx.x & 31;
    int n = blockIdx.x * 8 + w;
    if (n >= N_NODES) return;

    float cnt = fmaxf(g_cnt[n], 1.f);
    float h = fmaxf(g_agg1[(size_t)n * 32 + lane] / cnt + b1[lane], 0.f);
    g_h1h[(size_t)n * 32 + lane] = __float2half(h);

    float a0 = h * u2s[lane * 4 + 0];
    float a1 = h * u2s[lane * 4 + 1];
    float a2 = h * u2s[lane * 4 + 2];
    float a3 = h * u2s[lane * 4 + 3];
    #pragma unroll
    for (int off = 16; off; off >>= 1) {
        a0 += __shfl_xor_sync(0xffffffffu, a0, off);
        a1 += __shfl_xor_sync(0xffffffffu, a1, off);
        a2 += __shfl_xor_sync(0xffffffffu, a2, off);
        a3 += __shfl_xor_sync(0xffffffffu, a3, off);
    }
    if (lane == 0) g_hu2[n] = make_float4(a0, a1, a2, a3);
}

// ---------------- kernel M: zero agg2; xw2 = h1 @ w2 via wmma; coalesced stores ----
// 64 rows/block. acc frags staged through shared (32KB), then uint4 stores.
__global__ void k_xw2_wmma() {
    // fused zeroing of agg2 (800k float4), overlaps with MMA latency
    {
        int idx = blockIdx.x * blockDim.x + threadIdx.x;
        int stride = gridDim.x * blockDim.x;
        float4 z = make_float4(0.f, 0.f, 0.f, 0.f);
        for (int i = idx; i < N_NODES * 16; i += stride) ((float4*)g_agg2)[i] = z;
    }

    __shared__ __half obuf[64 * 256];  // 32KB
    int w = threadIdx.x >> 5;
    int col0 = (w & 3) * 64;
    int rsub = w >> 2;                 // 0 or 1

    wmma::fragment<wmma::matrix_b, 16, 16, 16, __half, wmma::row_major> b[4][2];
    #pragma unroll
    for (int c = 0; c < 4; c++) {
        wmma::load_matrix_sync(b[c][0], g_w2h + col0 + c * 16, 256);
        wmma::load_matrix_sync(b[c][1], g_w2h + 16 * 256 + col0 + c * 16, 256);
    }

    size_t base = (size_t)blockIdx.x * 64;
    #pragma unroll
    for (int rt = rsub; rt < 4; rt += 2) {
        size_t row0 = base + (size_t)rt * 16;
        wmma::fragment<wmma::matrix_a, 16, 16, 16, __half, wmma::row_major> a0, a1;
        wmma::load_matrix_sync(a0, g_h1h + row0 * 32, 32);
        wmma::load_matrix_sync(a1, g_h1h + row0 * 32 + 16, 32);
        #pragma unroll
        for (int c = 0; c < 4; c++) {
            wmma::fragment<wmma::accumulator, 16, 16, 16, __half> acc;
            wmma::fill_fragment(acc, __float2half(0.f));
            wmma::mma_sync(acc, a0, b[c][0], acc);
            wmma::mma_sync(acc, a1, b[c][1], acc);
            wmma::store_matrix_sync(obuf + (size_t)rt * 16 * 256 + col0 + c * 16, acc, 256,
                                    wmma::mem_row_major);
        }
    }
    __syncthreads();

    // coalesced copy shared -> global: 64*256 halfs = 2048 uint4; 8 per thread
    const uint4* src = (const uint4*)obuf;
    uint4* dst = (uint4*)(g_xw2r + base * 256);
    #pragma unroll
    for (int i = 0; i < 8; i++)
        dst[i * 256 + threadIdx.x] = src[i * 256 + threadIdx.x];
}

// ---------------- kernel D: conv2 edge pass (row-major fp16 gather) ----------------
__global__ void k_conv2_edge(const int* __restrict__ ei,
                             const float* __restrict__ c2) {
    float cc0 = __ldg(&c2[0]), cc1 = __ldg(&c2[1]), cc2 = __ldg(&c2[2]), cc3 = __ldg(&c2[3]);
    int w = threadIdx.x >> 5, lane = threadIdx.x & 31;
    int sub = lane >> 4, j = lane & 15;
    int e0 = (blockIdx.x * 8 + w) * 4 + sub * 2;
    if (e0 >= N_EDGES) return;
    int e1 = e0 + 1;

    int s0 = ei[e0], t0 = ei[N_EDGES + e0];
    int s1 = ei[e1], t1 = ei[N_EDGES + e1];

    float4 A0 = g_hu2[s0], B0 = g_hu2[t0];
    float4 A1 = g_hu2[s1], B1 = g_hu2[t1];

    const uint2* x0 = (const uint2*)(g_xw2r + (size_t)s0 * 256);
    const uint2* x1 = (const uint2*)(g_xw2r + (size_t)s1 * 256);
    uint2 w00 = x0[j], w01 = x0[16 + j], w02 = x0[32 + j], w03 = x0[48 + j];
    uint2 w10 = x1[j], w11 = x1[16 + j], w12 = x1[32 + j], w13 = x1[48 + j];

    float l0 = A0.x - B0.x + cc0, l1 = A0.y - B0.y + cc1;
    float l2 = A0.z - B0.z + cc2, l3 = A0.w - B0.w + cc3;
    float m = fmaxf(fmaxf(l0, l1), fmaxf(l2, l3));
    float q0 = __expf(l0 - m), q1 = __expf(l1 - m), q2 = __expf(l2 - m), q3 = __expf(l3 - m);
    float inv = 1.f / (q0 + q1 + q2 + q3);
    ull qa0 = pack2(q0 * inv), qa1 = pack2(q1 * inv), qa2 = pack2(q2 * inv), qa3 = pack2(q3 * inv);

    float k0 = A1.x - B1.x + cc0, k1 = A1.y - B1.y + cc1;
    float k2 = A1.z - B1.z + cc2, k3 = A1.w - B1.w + cc3;
    float mm = fmaxf(fmaxf(k0, k1), fmaxf(k2, k3));
    float r0 = __expf(k0 - mm), r1 = __expf(k1 - mm), r2 = __expf(k2 - mm), r3 = __expf(k3 - mm);
    float rinv = 1.f / (r0 + r1 + r2 + r3);
    ull qb0 = pack2(r0 * rinv), qb1 = pack2(r1 * rinv), qb2 = pack2(r2 * rinv), qb3 = pack2(r3 * rinv);

    ull m0a = 0ull, m0b = 0ull, m1a = 0ull, m1b = 0ull;
    m0a = f32x2_fma(qa0, h2_to_ull(w00.x), m0a);
    m0b = f32x2_fma(qa0, h2_to_ull(w00.y), m0b);
    m0a = f32x2_fma(qa1, h2_to_ull(w01.x), m0a);
    m0b = f32x2_fma(qa1, h2_to_ull(w01.y), m0b);
    m0a = f32x2_fma(qa2, h2_to_ull(w02.x), m0a);
    m0b = f32x2_fma(qa2, h2_to_ull(w02.y), m0b);
    m0a = f32x2_fma(qa3, h2_to_ull(w03.x), m0a);
    m0b = f32x2_fma(qa3, h2_to_ull(w03.y), m0b);
    m1a = f32x2_fma(qb0, h2_to_ull(w10.x), m1a);
    m1b = f32x2_fma(qb0, h2_to_ull(w10.y), m1b);
    m1a = f32x2_fma(qb1, h2_to_ull(w11.x), m1a);
    m1b = f32x2_fma(qb1, h2_to_ull(w11.y), m1b);
    m1a = f32x2_fma(qb2, h2_to_ull(w12.x), m1a);
    m1b = f32x2_fma(qb2, h2_to_ull(w12.y), m1b);
    m1a = f32x2_fma(qb3, h2_to_ull(w13.x), m1a);
    m1b = f32x2_fma(qb3, h2_to_ull(w13.y), m1b);

    float2 u0 = unpack2(m0a), v0 = unpack2(m0b);
    float2 u1v = unpack2(m1a), v1 = unpack2(m1b);
    red_add_v4(&g_agg2[(size_t)t0 * 64 + 4 * j], u0.x, u0.y, v0.x, v0.y);
    red_add_v4(&g_agg2[(size_t)t1 * 64 + 4 * j], u1v.x, u1v.y, v1.x, v1.y);
}

// ---------------- kernel E: h2 epilogue + pooling + fused head (last block) --------
__global__ void k_conv2_epi_pool(const float* __restrict__ b2,
                                 const int* __restrict__ batch,
                                 const float* __restrict__ fc1_w,
                                 const float* __restrict__ fc1_b,
                                 float* __restrict__ out) {
    __shared__ float pools[NGRAPHS * 64];
    __shared__ float gcnts[NGRAPHS];
    __shared__ int lastFlag;
    for (int i = threadIdx.x; i < NGRAPHS * 64; i += blockDim.x) pools[i] = 0.f;
    if (threadIdx.x < NGRAPHS) gcnts[threadIdx.x] = 0.f;
    __syncthreads();

    int w = threadIdx.x >> 5, lane = threadIdx.x & 31;
    int n = blockIdx.x * 8 + w;
    if (n < N_NODES) {
        float cnt = fmaxf(g_cnt[n], 1.f);
        int g = batch[n];
        float h0v = fmaxf(g_agg2[(size_t)n * 64 + lane]      / cnt + b2[lane],      0.f);
        float h1v = fmaxf(g_agg2[(size_t)n * 64 + 32 + lane] / cnt + b2[32 + lane], 0.f);
        atomicAdd(&pools[g * 64 + lane],      h0v);
        atomicAdd(&pools[g * 64 + 32 + lane], h1v);
        if (lane == 0) atomicAdd(&gcnts[g], 1.f);
    }
    __syncthreads();
    for (int i = threadIdx.x; i < NGRAPHS * 64; i += blockDim.x) atomicAdd(&g_pool[i], pools[i]);
    if (threadIdx.x < NGRAPHS) atomicAdd(&g_gcnt[threadIdx.x], gcnts[threadIdx.x]);

    // completion detection: last block computes the head
    __syncthreads();
    if (threadIdx.x == 0) {
        __threadfence();
        int old = atomicAdd(&g_done, 1);
        lastFlag = (old == (int)gridDim.x - 1);
    }
    __syncthreads();
    if (lastFlag) {
        int tid = threadIdx.x;
        if (tid < NGRAPHS * NCLASSES) {
            int g = tid / NCLASSES, j = tid % NCLASSES;
            float invn = 1.f / fmaxf(g_gcnt[g], 1.f);
            float acc = 0.f;
            #pragma unroll
            for (int c = 0; c < 64; c++) acc += g_pool[g * 64 + c] * fc1_w[c * NCLASSES + j];
            out[tid] = acc * invn + fc1_b[j];
        }
    }
}

// ---------------- launch ------------------------------------------------------------
extern "C" void kernel_launch(void* const* d_in, const int* in_sizes, int n_in,
                              void* d_out, int out_size) {
    const float* x     = (const float*)d_in[0];
    const int*   ei    = (const int*)d_in[1];
    const int*   batch = (const int*)d_in[2];
    const float* fc0_w = (const float*)d_in[3];
    const float* fc0_b = (const float*)d_in[4];
    const float* u1    = (const float*)d_in[5];
    const float* c1    = (const float*)d_in[6];
    const float* w1    = (const float*)d_in[7];
    const float* b1    = (const float*)d_in[8];
    const float* u2    = (const float*)d_in[9];
    const float* c2    = (const float*)d_in[10];
    const float* w2    = (const float*)d_in[11];
    const float* b2    = (const float*)d_in[12];
    const float* fc1_w = (const float*)d_in[13];
    const float* fc1_b = (const float*)d_in[14];
    float* out = (float*)d_out;

    k_fc0_xw1<<<(N_NODES + 31) / 32, 256>>>(x, fc0_w, fc0_b, w1, u1);
    k_conv1_edge<<<(N_EDGES + 63) / 64, 256>>>(ei, c1);
    k_h1<<<(N_NODES + 7) / 8, 256>>>(b1, u2, w2);
    k_xw2_wmma<<<M_PAD / 64, 256>>>();
    k_conv2_edge<<<(N_EDGES + 31) / 32, 256>>>(ei, c2);
    k_conv2_epi_pool<<<(N_NODES + 7) / 8, 256>>>(b2, batch, fc1_w, fc1_b, out);
}